// round 3
// baseline (speedup 1.0000x reference)
#include <cuda_runtime.h>
#include <math.h>
#include <stdint.h>

#define HCH   32
#define NMAX  50000
#define EMAX  800000
#define NGR   128

// ---------------- scratch (static device arrays: no allocations) ----------------
__device__ float g_raw[(size_t)NMAX * 128];   // pre-activation node features (N,4,32)
__device__ float g_act[(size_t)NMAX * 128];   // post-activation node features (N,4,32)
__device__ float g_h3 [(size_t)NMAX * 32];    // layer-3 scalar output (N,32)
__device__ float g_pool[NGR * 32];            // graph pooled (128,32)

// ---------------- helpers ----------------
__device__ __forceinline__ float sspf(float x) {
    // softplus(x) - ln(2), numerically stable
    return fmaxf(x, 0.f) + log1pf(__expf(-fabsf(x))) - 0.69314718055994530942f;
}

__device__ __forceinline__ void red_add_v4(float* p, float a, float b, float c, float d) {
    asm volatile("red.global.add.v4.f32 [%0], {%1,%2,%3,%4};"
                 :: "l"(p), "f"(a), "f"(b), "f"(c), "f"(d) : "memory");
}

// lane = channel. Pack 4 consecutive channels into one vec4 reduction.
__device__ __forceinline__ void scatter_row(float* basep, int lane, float v) {
    float v1 = __shfl_down_sync(0xffffffffu, v, 1);
    float v2 = __shfl_down_sync(0xffffffffu, v, 2);
    float v3 = __shfl_down_sync(0xffffffffu, v, 3);
    if ((lane & 3) == 0) red_add_v4(basep + lane, v, v1, v2, v3);
}

__device__ __forceinline__ float cutoff_w(float d) {
    float u = d * (1.0f / 1.5f);
    if (u >= 1.f) return 0.f;
    float u2 = u * u;
    float u6 = u2 * u2 * u2;
    return 1.f + u6 * (-28.f + u * (48.f - 21.f * u));
}

__device__ __forceinline__ float emb_lane(float d, int lane) {
    if (lane >= 10) return 0.f;
    float mu = 0.7f + (float)lane * 0.111111111111111111f;  // linspace(0.7,1.7,10)
    float t = d - mu;
    return __expf(-50.f * t * t);   // exp(-(d-mu)^2 / (2*0.1^2))
}

// ---------------- layer 1: scalar input -> (l0,l1) message, scatter to g_raw ----------------
__global__ void k_layer1(const float* __restrict__ x, const float* __restrict__ esh,
                         const float* __restrict__ elen, const int* __restrict__ ei,
                         const float* __restrict__ W1, const float* __restrict__ b1, int E)
{
    int gw = (blockIdx.x * blockDim.x + threadIdx.x) >> 5;
    if (gw >= E) return;
    int lane = threadIdx.x & 31;
    int src = __ldg(&ei[gw]);
    int dst = __ldg(&ei[E + gw]);
    float d = __ldg(&elen[gw]);
    float embv = emb_lane(d, lane);
    float ew = cutoff_w(d);

    float wa = __ldg(&b1[lane]);
    float wb = __ldg(&b1[32 + lane]);
    #pragma unroll
    for (int k = 0; k < 10; k++) {
        float ek = __shfl_sync(0xffffffffu, embv, k);
        wa = fmaf(ek, __ldg(&W1[k * 64 + lane]), wa);
        wb = fmaf(ek, __ldg(&W1[k * 64 + 32 + lane]), wb);
    }
    const float* she = esh + (size_t)gw * 9;
    float s0  = __ldg(she + 0);
    float sv0 = __ldg(she + 1), sv1 = __ldg(she + 2), sv2 = __ldg(she + 3);
    float xs = __ldg(&x[src]) * ew;

    float* outp = g_raw + (size_t)dst * 128;
    scatter_row(outp,      lane, xs * s0  * wa);
    scatter_row(outp + 32, lane, xs * sv0 * wb);
    scatter_row(outp + 64, lane, xs * sv1 * wb);
    scatter_row(outp + 96, lane, xs * sv2 * wb);
}

// ---------------- norm-act: g_raw -> g_act ----------------
__global__ void k_normact(int N)
{
    int t = blockIdx.x * blockDim.x + threadIdx.x;
    if (t >= N * 32) return;
    int n = t >> 5, c = t & 31;
    const float* ip = g_raw + (size_t)n * 128;
    float s  = ip[c];
    float v0 = ip[32 + c], v1 = ip[64 + c], v2 = ip[96 + c];
    float nr = sqrtf(v0 * v0 + v1 * v1 + v2 * v2 + 1e-12f);
    float sc = sspf(nr) / nr;
    float* op = g_act + (size_t)n * 128;
    op[c]      = sspf(s);
    op[32 + c] = v0 * sc;
    op[64 + c] = v1 * sc;
    op[96 + c] = v2 * sc;
}

// ---------------- layer 2: full 6-path channel-wise TFN layer ----------------
__global__ void k_layer2(const float* __restrict__ esh, const float* __restrict__ elen,
                         const int* __restrict__ ei, const float* __restrict__ W2,
                         const float* __restrict__ b2, int E)
{
    int gw = (blockIdx.x * blockDim.x + threadIdx.x) >> 5;
    if (gw >= E) return;
    int lane = threadIdx.x & 31;
    int src = __ldg(&ei[gw]);
    int dst = __ldg(&ei[E + gw]);
    float d = __ldg(&elen[gw]);
    float embv = emb_lane(d, lane);
    float ew = cutoff_w(d);

    float wp0 = __ldg(&b2[lane]),        wp1 = __ldg(&b2[32 + lane]);
    float wp2 = __ldg(&b2[64 + lane]),   wp3 = __ldg(&b2[96 + lane]);
    float wp4 = __ldg(&b2[128 + lane]),  wp5 = __ldg(&b2[160 + lane]);
    #pragma unroll
    for (int k = 0; k < 10; k++) {
        float ek = __shfl_sync(0xffffffffu, embv, k);
        const float* wr = W2 + k * 192;
        wp0 = fmaf(ek, __ldg(wr + lane),        wp0);
        wp1 = fmaf(ek, __ldg(wr + 32 + lane),   wp1);
        wp2 = fmaf(ek, __ldg(wr + 64 + lane),   wp2);
        wp3 = fmaf(ek, __ldg(wr + 96 + lane),   wp3);
        wp4 = fmaf(ek, __ldg(wr + 128 + lane),  wp4);
        wp5 = fmaf(ek, __ldg(wr + 160 + lane),  wp5);
    }

    const float* she = esh + (size_t)gw * 9;
    float s0  = __ldg(she + 0);
    float sv0 = __ldg(she + 1), sv1 = __ldg(she + 2), sv2 = __ldg(she + 3);
    float t20 = __ldg(she + 4), t21 = __ldg(she + 5), t22 = __ldg(she + 6);
    float t23 = __ldg(she + 7), t24 = __ldg(she + 8);

    const float* xp = g_act + (size_t)src * 128;
    float x0  = xp[lane];
    float xv0 = xp[32 + lane], xv1 = xp[64 + lane], xv2 = xp[96 + lane];

    const float RT3I = 0.57735026918962576451f;  // 1/sqrt(3)
    const float RT2I = 0.70710678118654752440f;  // 1/sqrt(2)
    const float A    = 0.31622776601683793320f;  // 1/sqrt(10)
    const float B    = 0.54772255750516611346f;  // sqrt(3/10)

    // path (1,1,0): -1/sqrt3 * dot ; path (0,0,0)
    float dotv = xv0 * sv0 + xv1 * sv1 + xv2 * sv2;
    float m0 = s0 * x0 * wp0 - RT3I * dotv * wp3;

    // path (1,1,1): -1/sqrt2 * cross
    float cr0 = xv1 * sv2 - xv2 * sv1;
    float cr1 = xv2 * sv0 - xv0 * sv2;
    float cr2 = xv0 * sv1 - xv1 * sv0;

    // path (1,2,1): real CG(1,2,1) contraction (11 nonzeros)
    float t50 =  A * xv0 * t22 + B * xv0 * t24 - B * xv1 * t21 - B * xv2 * t20;
    float t51 = -B * xv0 * t21 - 2.f * A * xv1 * t22 - B * xv2 * t23;
    float t52 = -B * xv0 * t20 - B * xv1 * t23 + A * xv2 * t22 - B * xv2 * t24;

    float m1 = x0 * sv0 * wp1 + xv0 * s0 * wp2 - RT2I * cr0 * wp4 + t50 * wp5;
    float m2 = x0 * sv1 * wp1 + xv1 * s0 * wp2 - RT2I * cr1 * wp4 + t51 * wp5;
    float m3 = x0 * sv2 * wp1 + xv2 * s0 * wp2 - RT2I * cr2 * wp4 + t52 * wp5;

    float* outp = g_raw + (size_t)dst * 128;
    scatter_row(outp,      lane, m0 * ew);
    scatter_row(outp + 32, lane, m1 * ew);
    scatter_row(outp + 64, lane, m2 * ew);
    scatter_row(outp + 96, lane, m3 * ew);
}

// ---------------- layer 3: scalar output only ----------------
__global__ void k_layer3(const float* __restrict__ esh, const float* __restrict__ elen,
                         const int* __restrict__ ei, const float* __restrict__ W3,
                         const float* __restrict__ b3, int E)
{
    int gw = (blockIdx.x * blockDim.x + threadIdx.x) >> 5;
    if (gw >= E) return;
    int lane = threadIdx.x & 31;
    int src = __ldg(&ei[gw]);
    int dst = __ldg(&ei[E + gw]);
    float d = __ldg(&elen[gw]);
    float embv = emb_lane(d, lane);
    float ew = cutoff_w(d);

    float wa = __ldg(&b3[lane]);
    float wb = __ldg(&b3[32 + lane]);
    #pragma unroll
    for (int k = 0; k < 10; k++) {
        float ek = __shfl_sync(0xffffffffu, embv, k);
        wa = fmaf(ek, __ldg(&W3[k * 64 + lane]), wa);
        wb = fmaf(ek, __ldg(&W3[k * 64 + 32 + lane]), wb);
    }

    const float* she = esh + (size_t)gw * 9;
    float s0  = __ldg(she + 0);
    float sv0 = __ldg(she + 1), sv1 = __ldg(she + 2), sv2 = __ldg(she + 3);

    const float* xp = g_act + (size_t)src * 128;
    float x0  = xp[lane];
    float xv0 = xp[32 + lane], xv1 = xp[64 + lane], xv2 = xp[96 + lane];

    const float RT3I = 0.57735026918962576451f;
    float dotv = xv0 * sv0 + xv1 * sv1 + xv2 * sv2;
    float m0 = ew * (x0 * s0 * wa - RT3I * dotv * wb);

    scatter_row(g_h3 + (size_t)dst * 32, lane, m0);
}

// ---------------- silu + graph pooling ----------------
__global__ void k_pool(const int* __restrict__ batch, int N)
{
    int t = blockIdx.x * blockDim.x + threadIdx.x;
    if (t >= N * 32) return;
    int n = t >> 5, c = t & 31;
    float h = g_h3[(size_t)n * 32 + c];
    float y = h / (1.f + __expf(-h));   // silu
    atomicAdd(&g_pool[__ldg(&batch[n]) * 32 + c], y);
}

// ---------------- head: (128,32) @ (32,8) + bias -> softmax ----------------
__global__ void k_head(const float* __restrict__ Wo, const float* __restrict__ bo,
                       float* __restrict__ out)
{
    __shared__ float Ws[32 * 8];
    __shared__ float bs[8];
    int t = threadIdx.x;
    if (t < 256) Ws[t] = Wo[t];
    if (t < 8)   bs[t] = bo[t];
    __syncthreads();
    if (t < NGR) {
        float acc[8];
        #pragma unroll
        for (int j = 0; j < 8; j++) acc[j] = bs[j];
        #pragma unroll
        for (int k = 0; k < 32; k++) {
            float gv = g_pool[t * 32 + k];
            #pragma unroll
            for (int j = 0; j < 8; j++) acc[j] = fmaf(gv, Ws[k * 8 + j], acc[j]);
        }
        float mx = acc[0];
        #pragma unroll
        for (int j = 1; j < 8; j++) mx = fmaxf(mx, acc[j]);
        float sm = 0.f;
        #pragma unroll
        for (int j = 0; j < 8; j++) { acc[j] = __expf(acc[j] - mx); sm += acc[j]; }
        float inv = 1.f / sm;
        #pragma unroll
        for (int j = 0; j < 8; j++) out[t * 8 + j] = acc[j] * inv;
    }
}

// ---------------- host ----------------
extern "C" void kernel_launch(void* const* d_in, const int* in_sizes, int n_in,
                              void* d_out, int out_size)
{
    // Two plausible metadata orders; disambiguate by sizes.
    // Order A (reference signature): x, edge_sh, edge_len, W1,b1,W2,b2,W3,b3,Wo,bo, edge_index, batch
    // Order B (setup_inputs dict):   x, edge_index, edge_sh, edge_len, batch, W1,b1,W2,b2,W3,b3,Wo,bo
    int ix, ish, ilen, iW1, ib1, iW2, ib2, iW3, ib3, iWo, ibo, iei, ibatch;
    if (n_in >= 13 && (long long)in_sizes[1] == 9LL * (long long)in_sizes[2]) {
        ix = 0; ish = 1; ilen = 2; iW1 = 3; ib1 = 4; iW2 = 5; ib2 = 6;
        iW3 = 7; ib3 = 8; iWo = 9; ibo = 10; iei = 11; ibatch = 12;
    } else {
        ix = 0; iei = 1; ish = 2; ilen = 3; ibatch = 4; iW1 = 5; ib1 = 6;
        iW2 = 7; ib2 = 8; iW3 = 9; ib3 = 10; iWo = 11; ibo = 12;
    }

    const float* x     = (const float*)d_in[ix];
    const float* esh   = (const float*)d_in[ish];
    const float* elen  = (const float*)d_in[ilen];
    const float* W1    = (const float*)d_in[iW1];
    const float* b1    = (const float*)d_in[ib1];
    const float* W2    = (const float*)d_in[iW2];
    const float* b2    = (const float*)d_in[ib2];
    const float* W3    = (const float*)d_in[iW3];
    const float* b3    = (const float*)d_in[ib3];
    const float* Wo    = (const float*)d_in[iWo];
    const float* bo    = (const float*)d_in[ibo];
    const int*   ei    = (const int*)d_in[iei];
    const int*   batch = (const int*)d_in[ibatch];

    int N = in_sizes[ix];      // x is (N,1)
    int E = in_sizes[ilen];    // edge_len is (E,)
    if (N > NMAX) N = NMAX;
    if (E > EMAX) E = EMAX;

    void *praw, *ph3, *ppool;
    cudaGetSymbolAddress(&praw, g_raw);
    cudaGetSymbolAddress(&ph3, g_h3);
    cudaGetSymbolAddress(&ppool, g_pool);

    int nbE = (E * 32 + 255) / 256;
    int nbN = (N * 32 + 255) / 256;

    // Layer 1
    cudaMemsetAsync(praw, 0, (size_t)N * 128 * sizeof(float), 0);
    k_layer1<<<nbE, 256>>>(x, esh, elen, ei, W1, b1, E);
    k_normact<<<nbN, 256>>>(N);

    // Layer 2
    cudaMemsetAsync(praw, 0, (size_t)N * 128 * sizeof(float), 0);
    k_layer2<<<nbE, 256>>>(esh, elen, ei, W2, b2, E);
    k_normact<<<nbN, 256>>>(N);

    // Layer 3 + pooling + head
    cudaMemsetAsync(ph3, 0, (size_t)N * 32 * sizeof(float), 0);
    cudaMemsetAsync(ppool, 0, (size_t)NGR * 32 * sizeof(float), 0);
    k_layer3<<<nbE, 256>>>(esh, elen, ei, W3, b3, E);
    k_pool<<<nbN, 256>>>(batch, N);
    k_head<<<1, 256>>>(Wo, bo, (float*)d_out);
}

// round 4
// speedup vs baseline: 1.7743x; 1.7743x over previous
#include <cuda_runtime.h>
#include <math.h>
#include <stdint.h>

#define HCH   32
#define NMAX  50000
#define EMAX  800000
#define NGR   128
#define EB    4          // edges per warp

// ---------------- scratch (static device arrays: no allocations) ----------------
__device__ float g_raw[(size_t)NMAX * 128];   // pre-activation node features (N,4,32)
__device__ float g_act[(size_t)NMAX * 128];   // post-activation node features (N,4,32)
__device__ float g_h3 [(size_t)NMAX * 32];    // layer-3 scalar output (N,32)
__device__ float g_pool[NGR * 32];            // graph pooled (128,32)

// ---------------- helpers ----------------
__device__ __forceinline__ float sspf(float x) {
    // softplus(x) - ln(2), numerically stable
    return fmaxf(x, 0.f) + log1pf(__expf(-fabsf(x))) - 0.69314718055994530942f;
}

__device__ __forceinline__ void red_add(float* p, float v) {
    asm volatile("red.global.add.f32 [%0], %1;" :: "l"(p), "f"(v) : "memory");
}

__device__ __forceinline__ float cutoff_w(float d) {
    float u = d * (1.0f / 1.5f);
    if (u >= 1.f) return 0.f;
    float u2 = u * u;
    float u6 = u2 * u2 * u2;
    return 1.f + u6 * (-28.f + u * (48.f - 21.f * u));
}

__device__ __forceinline__ float emb_lane(float d, int lane) {
    if (lane >= 10) return 0.f;
    float mu = 0.7f + (float)lane * 0.111111111111111111f;  // linspace(0.7,1.7,10)
    float t = d - mu;
    return __expf(-50.f * t * t);   // exp(-(d-mu)^2 / (2*0.1^2))
}

// ---------------- layer 1: scalar input -> (l0,l1) message, scatter to g_raw ----------------
__global__ void __launch_bounds__(256) k_layer1(
    const float* __restrict__ x, const float* __restrict__ esh,
    const float* __restrict__ elen, const int* __restrict__ ei,
    const float* __restrict__ W1, const float* __restrict__ b1, int E)
{
    int warp = (blockIdx.x * blockDim.x + threadIdx.x) >> 5;
    int lane = threadIdx.x & 31;
    int e0 = warp * EB;
    if (e0 >= E) return;

    int src[EB], dst[EB];
    float ew[EB], embv[EB];
    #pragma unroll
    for (int e = 0; e < EB; e++) {
        int idx = e0 + e;
        bool v = idx < E;
        int id2 = v ? idx : 0;
        src[e] = ei[id2];
        dst[e] = ei[E + id2];
        float d = elen[id2];
        ew[e] = v ? cutoff_w(d) : 0.f;
        embv[e] = emb_lane(d, lane);
    }

    float wa[EB], wb[EB];
    {
        float b0 = b1[lane], b1v = b1[32 + lane];
        #pragma unroll
        for (int e = 0; e < EB; e++) { wa[e] = b0; wb[e] = b1v; }
    }
    #pragma unroll
    for (int k = 0; k < 10; k++) {
        float w0 = W1[k * 64 + lane];
        float w1 = W1[k * 64 + 32 + lane];
        #pragma unroll
        for (int e = 0; e < EB; e++) {
            float ek = __shfl_sync(0xffffffffu, embv[e], k);
            wa[e] = fmaf(ek, w0, wa[e]);
            wb[e] = fmaf(ek, w1, wb[e]);
        }
    }

    #pragma unroll
    for (int e = 0; e < EB; e++) {
        const float* she = esh + (size_t)(e0 + e < E ? e0 + e : 0) * 9;
        float s0  = she[0];
        float sv0 = she[1], sv1 = she[2], sv2 = she[3];
        float xs = x[src[e]] * ew[e];

        float* outp = g_raw + (size_t)dst[e] * 128 + lane;
        red_add(outp,      xs * s0  * wa[e]);
        red_add(outp + 32, xs * sv0 * wb[e]);
        red_add(outp + 64, xs * sv1 * wb[e]);
        red_add(outp + 96, xs * sv2 * wb[e]);
    }
}

// ---------------- norm-act: g_raw -> g_act (optionally zero g_raw for next layer) ----------------
__global__ void k_normact(int N, int zero_raw)
{
    int t = blockIdx.x * blockDim.x + threadIdx.x;
    if (t >= N * 32) return;
    int n = t >> 5, c = t & 31;
    float* ip = g_raw + (size_t)n * 128;
    float s  = ip[c];
    float v0 = ip[32 + c], v1 = ip[64 + c], v2 = ip[96 + c];
    float nr = sqrtf(v0 * v0 + v1 * v1 + v2 * v2 + 1e-12f);
    float sc = sspf(nr) / nr;
    float* op = g_act + (size_t)n * 128;
    op[c]      = sspf(s);
    op[32 + c] = v0 * sc;
    op[64 + c] = v1 * sc;
    op[96 + c] = v2 * sc;
    if (zero_raw) {
        ip[c] = 0.f; ip[32 + c] = 0.f; ip[64 + c] = 0.f; ip[96 + c] = 0.f;
    }
}

// ---------------- layer 2: full 6-path channel-wise TFN layer ----------------
__global__ void __launch_bounds__(256) k_layer2(
    const float* __restrict__ esh, const float* __restrict__ elen,
    const int* __restrict__ ei, const float* __restrict__ W2,
    const float* __restrict__ b2, int E)
{
    int warp = (blockIdx.x * blockDim.x + threadIdx.x) >> 5;
    int lane = threadIdx.x & 31;
    int e0 = warp * EB;
    if (e0 >= E) return;

    int src[EB], dst[EB];
    float ew[EB], embv[EB];
    #pragma unroll
    for (int e = 0; e < EB; e++) {
        int idx = e0 + e;
        bool v = idx < E;
        int id2 = v ? idx : 0;
        src[e] = ei[id2];
        dst[e] = ei[E + id2];
        float d = elen[id2];
        ew[e] = v ? cutoff_w(d) : 0.f;
        embv[e] = emb_lane(d, lane);
    }

    float wp[6][EB];
    #pragma unroll
    for (int p = 0; p < 6; p++) {
        float bv = b2[p * 32 + lane];
        #pragma unroll
        for (int e = 0; e < EB; e++) wp[p][e] = bv;
    }
    #pragma unroll
    for (int k = 0; k < 10; k++) {
        float w[6];
        #pragma unroll
        for (int p = 0; p < 6; p++) w[p] = W2[k * 192 + p * 32 + lane];
        #pragma unroll
        for (int e = 0; e < EB; e++) {
            float ek = __shfl_sync(0xffffffffu, embv[e], k);
            #pragma unroll
            for (int p = 0; p < 6; p++) wp[p][e] = fmaf(ek, w[p], wp[p][e]);
        }
    }

    const float RT3I = 0.57735026918962576451f;  // 1/sqrt(3)
    const float RT2I = 0.70710678118654752440f;  // 1/sqrt(2)
    const float A    = 0.31622776601683793320f;  // 1/sqrt(10)
    const float B    = 0.54772255750516611346f;  // sqrt(3/10)

    #pragma unroll
    for (int e = 0; e < EB; e++) {
        const float* she = esh + (size_t)(e0 + e < E ? e0 + e : 0) * 9;
        float s0  = she[0];
        float sv0 = she[1], sv1 = she[2], sv2 = she[3];
        float t20 = she[4], t21 = she[5], t22 = she[6];
        float t23 = she[7], t24 = she[8];

        const float* xp = g_act + (size_t)src[e] * 128 + lane;
        float x0  = xp[0];
        float xv0 = xp[32], xv1 = xp[64], xv2 = xp[96];

        // path (0,0,0) + path (1,1,0): -1/sqrt3 * dot
        float dotv = xv0 * sv0 + xv1 * sv1 + xv2 * sv2;
        float m0 = s0 * x0 * wp[0][e] - RT3I * dotv * wp[3][e];

        // path (1,1,1): -1/sqrt2 * cross
        float cr0 = xv1 * sv2 - xv2 * sv1;
        float cr1 = xv2 * sv0 - xv0 * sv2;
        float cr2 = xv0 * sv1 - xv1 * sv0;

        // path (1,2,1): real CG(1,2,1) contraction (11 nonzeros)
        float t50 =  A * xv0 * t22 + B * xv0 * t24 - B * xv1 * t21 - B * xv2 * t20;
        float t51 = -B * xv0 * t21 - 2.f * A * xv1 * t22 - B * xv2 * t23;
        float t52 = -B * xv0 * t20 - B * xv1 * t23 + A * xv2 * t22 - B * xv2 * t24;

        float m1 = x0 * sv0 * wp[1][e] + xv0 * s0 * wp[2][e] - RT2I * cr0 * wp[4][e] + t50 * wp[5][e];
        float m2 = x0 * sv1 * wp[1][e] + xv1 * s0 * wp[2][e] - RT2I * cr1 * wp[4][e] + t51 * wp[5][e];
        float m3 = x0 * sv2 * wp[1][e] + xv2 * s0 * wp[2][e] - RT2I * cr2 * wp[4][e] + t52 * wp[5][e];

        float* outp = g_raw + (size_t)dst[e] * 128 + lane;
        float w = ew[e];
        red_add(outp,      m0 * w);
        red_add(outp + 32, m1 * w);
        red_add(outp + 64, m2 * w);
        red_add(outp + 96, m3 * w);
    }
}

// ---------------- layer 3: scalar output only ----------------
__global__ void __launch_bounds__(256) k_layer3(
    const float* __restrict__ esh, const float* __restrict__ elen,
    const int* __restrict__ ei, const float* __restrict__ W3,
    const float* __restrict__ b3, int E)
{
    int warp = (blockIdx.x * blockDim.x + threadIdx.x) >> 5;
    int lane = threadIdx.x & 31;
    int e0 = warp * EB;
    if (e0 >= E) return;

    int src[EB], dst[EB];
    float ew[EB], embv[EB];
    #pragma unroll
    for (int e = 0; e < EB; e++) {
        int idx = e0 + e;
        bool v = idx < E;
        int id2 = v ? idx : 0;
        src[e] = ei[id2];
        dst[e] = ei[E + id2];
        float d = elen[id2];
        ew[e] = v ? cutoff_w(d) : 0.f;
        embv[e] = emb_lane(d, lane);
    }

    float wa[EB], wb[EB];
    {
        float b0 = b3[lane], b1v = b3[32 + lane];
        #pragma unroll
        for (int e = 0; e < EB; e++) { wa[e] = b0; wb[e] = b1v; }
    }
    #pragma unroll
    for (int k = 0; k < 10; k++) {
        float w0 = W3[k * 64 + lane];
        float w1 = W3[k * 64 + 32 + lane];
        #pragma unroll
        for (int e = 0; e < EB; e++) {
            float ek = __shfl_sync(0xffffffffu, embv[e], k);
            wa[e] = fmaf(ek, w0, wa[e]);
            wb[e] = fmaf(ek, w1, wb[e]);
        }
    }

    const float RT3I = 0.57735026918962576451f;
    #pragma unroll
    for (int e = 0; e < EB; e++) {
        const float* she = esh + (size_t)(e0 + e < E ? e0 + e : 0) * 9;
        float s0  = she[0];
        float sv0 = she[1], sv1 = she[2], sv2 = she[3];

        const float* xp = g_act + (size_t)src[e] * 128 + lane;
        float x0  = xp[0];
        float xv0 = xp[32], xv1 = xp[64], xv2 = xp[96];

        float dotv = xv0 * sv0 + xv1 * sv1 + xv2 * sv2;
        float m0 = ew[e] * (x0 * s0 * wa[e] - RT3I * dotv * wb[e]);

        red_add(g_h3 + (size_t)dst[e] * 32 + lane, m0);
    }
}

// ---------------- silu + graph pooling ----------------
__global__ void k_pool(const int* __restrict__ batch, int N)
{
    int t = blockIdx.x * blockDim.x + threadIdx.x;
    if (t >= N * 32) return;
    int n = t >> 5, c = t & 31;
    float h = g_h3[(size_t)n * 32 + c];
    float y = h / (1.f + __expf(-h));   // silu
    atomicAdd(&g_pool[__ldg(&batch[n]) * 32 + c], y);
}

// ---------------- head: (128,32) @ (32,8) + bias -> softmax ----------------
__global__ void k_head(const float* __restrict__ Wo, const float* __restrict__ bo,
                       float* __restrict__ out)
{
    __shared__ float Ws[32 * 8];
    __shared__ float bs[8];
    int t = threadIdx.x;
    if (t < 256) Ws[t] = Wo[t];
    if (t < 8)   bs[t] = bo[t];
    __syncthreads();
    if (t < NGR) {
        float acc[8];
        #pragma unroll
        for (int j = 0; j < 8; j++) acc[j] = bs[j];
        #pragma unroll
        for (int k = 0; k < 32; k++) {
            float gv = g_pool[t * 32 + k];
            #pragma unroll
            for (int j = 0; j < 8; j++) acc[j] = fmaf(gv, Ws[k * 8 + j], acc[j]);
        }
        float mx = acc[0];
        #pragma unroll
        for (int j = 1; j < 8; j++) mx = fmaxf(mx, acc[j]);
        float sm = 0.f;
        #pragma unroll
        for (int j = 0; j < 8; j++) { acc[j] = __expf(acc[j] - mx); sm += acc[j]; }
        float inv = 1.f / sm;
        #pragma unroll
        for (int j = 0; j < 8; j++) out[t * 8 + j] = acc[j] * inv;
    }
}

// ---------------- host ----------------
extern "C" void kernel_launch(void* const* d_in, const int* in_sizes, int n_in,
                              void* d_out, int out_size)
{
    // Two plausible metadata orders; disambiguate by sizes.
    int ix, ish, ilen, iW1, ib1, iW2, ib2, iW3, ib3, iWo, ibo, iei, ibatch;
    if (n_in >= 13 && (long long)in_sizes[1] == 9LL * (long long)in_sizes[2]) {
        ix = 0; ish = 1; ilen = 2; iW1 = 3; ib1 = 4; iW2 = 5; ib2 = 6;
        iW3 = 7; ib3 = 8; iWo = 9; ibo = 10; iei = 11; ibatch = 12;
    } else {
        ix = 0; iei = 1; ish = 2; ilen = 3; ibatch = 4; iW1 = 5; ib1 = 6;
        iW2 = 7; ib2 = 8; iW3 = 9; ib3 = 10; iWo = 11; ibo = 12;
    }

    const float* x     = (const float*)d_in[ix];
    const float* esh   = (const float*)d_in[ish];
    const float* elen  = (const float*)d_in[ilen];
    const float* W1    = (const float*)d_in[iW1];
    const float* b1    = (const float*)d_in[ib1];
    const float* W2    = (const float*)d_in[iW2];
    const float* b2    = (const float*)d_in[ib2];
    const float* W3    = (const float*)d_in[iW3];
    const float* b3    = (const float*)d_in[ib3];
    const float* Wo    = (const float*)d_in[iWo];
    const float* bo    = (const float*)d_in[ibo];
    const int*   ei    = (const int*)d_in[iei];
    const int*   batch = (const int*)d_in[ibatch];

    int N = in_sizes[ix];      // x is (N,1)
    int E = in_sizes[ilen];    // edge_len is (E,)
    if (N > NMAX) N = NMAX;
    if (E > EMAX) E = EMAX;

    void *praw, *ph3, *ppool;
    cudaGetSymbolAddress(&praw, g_raw);
    cudaGetSymbolAddress(&ph3, g_h3);
    cudaGetSymbolAddress(&ppool, g_pool);

    int nwarps = (E + EB - 1) / EB;
    int nbE = (nwarps * 32 + 255) / 256;
    int nbN = (N * 32 + 255) / 256;

    // Layer 1
    cudaMemsetAsync(praw, 0, (size_t)N * 128 * sizeof(float), 0);
    k_layer1<<<nbE, 256>>>(x, esh, elen, ei, W1, b1, E);
    k_normact<<<nbN, 256>>>(N, /*zero_raw=*/1);   // also zeroes g_raw for layer 2

    // Layer 2
    k_layer2<<<nbE, 256>>>(esh, elen, ei, W2, b2, E);
    k_normact<<<nbN, 256>>>(N, /*zero_raw=*/0);

    // Layer 3 + pooling + head
    cudaMemsetAsync(ph3, 0, (size_t)N * 32 * sizeof(float), 0);
    cudaMemsetAsync(ppool, 0, (size_t)NGR * 32 * sizeof(float), 0);
    k_layer3<<<nbE, 256>>>(esh, elen, ei, W3, b3, E);
    k_pool<<<nbN, 256>>>(batch, N);
    k_head<<<1, 256>>>(Wo, bo, (float*)d_out);
}